// round 10
// baseline (speedup 1.0000x reference)
#include <cuda_runtime.h>
#include <cstdint>

#define L2E 1.4426950408889634f
#define NBLK 256
#define NTHR 256
#define ZP 21   // padded z stride in smem

// ---------------- device scratch (static, no runtime alloc) ----------------
__device__ float g_act[64u * 131072u];  // quad-interleaved [16][B][4]
__device__ float g_statA[352];          // per group: 8 sums + 36 sym-cov
__device__ float g_stat2[20];           // sumsq[20] of z~
__device__ int   g_bar1, g_bar2;        // spin barriers

__device__ __forceinline__ float ex2f(float x) {
    float y; asm("ex2.approx.ftz.f32 %0, %1;" : "=f"(y) : "f"(x)); return y;
}

#define FMA_F32X2(d, a, b, c) \
    asm("fma.rn.f32x2 %0, %1, %2, %3;" : "=l"(d) : "l"(a), "l"(b), "l"(c))
#define PACK_DUP(d, f) \
    asm("mov.b64 %0, {%1, %1};" : "=l"(d) : "f"(f))
#define UNPACK2(lo, hi, v) \
    asm("mov.b64 {%0, %1}, %2;" : "=f"(lo), "=f"(hi) : "l"(v))

__device__ __forceinline__ void grid_barrier(int* bar) {
    __syncthreads();
    __threadfence();                    // release: my writes visible
    if (threadIdx.x == 0) {
        atomicAdd(bar, 1);
        while (*((volatile int*)bar) < NBLK) { }
    }
    __syncthreads();
    __threadfence();                    // acquire before reading others' data
}

// ---------------- K0: zero accumulators + barrier counters ----------------
__global__ void k0_zero() {
    int t = threadIdx.x;
    if (t < 352) g_statA[t] = 0.f;
    if (t < 20)  g_stat2[t] = 0.f;
    if (t == 0) { g_bar1 = 0; g_bar2 = 0; }
}

// ---------------- fused persistent kernel ----------------
__global__ __launch_bounds__(NTHR, 2) void k_fused(
    const float* __restrict__ x,
    const float* __restrict__ centres,   // [8][8]
    const float* __restrict__ logw,      // [8][8]
    const float* __restrict__ rbw,       // [8][8]
    const float* __restrict__ linw,      // [8]
    const float* __restrict__ pW,        // [8][16][8]
    const float* __restrict__ g1,        // bn1_gamma [128]
    const float* __restrict__ fpW,       // [20][128]
    const float* __restrict__ g2v,       // bn2_gamma [20]
    const float* __restrict__ b2v,       // bn2_beta [20]
    const float* __restrict__ fzc,       // [10][20]
    const float* __restrict__ lsu,       // [10][20]
    const float* __restrict__ lsl,       // [10][20]
    const float* __restrict__ hW,        // [1][10]
    const float* __restrict__ hb,        // [1]
    float* __restrict__ out, int B, float invB)
{
    __shared__ __align__(16) float zsh[512 * ZP];   // z~ rows, 43KB
    __shared__ __align__(16) float Msh[64 * 20];    // combined weights [ch][j]
    __shared__ float4 fzsh[200];
    __shared__ float sm[352];                        // stat reduce / reuse
    __shared__ float s1sh[128];
    __shared__ float s2s[20], t2s[20], wrs[10];
    __shared__ float b0s;

    int tid = threadIdx.x;
    size_t B4 = (size_t)B * 4;

    // ================= P1: act = KAN-RBF(x), per-group stats =================
    {
        int slot = blockIdx.x * NTHR + tid;
        int g = slot & 7;
        int row0 = slot >> 3;
        int rowsInFlight = NBLK * NTHR / 8;

        float A[8], Bc[8], Gc[8], W[8];
#pragma unroll
        for (int k = 0; k < 8; k++) {
            float sig = __expf(logw[g * 8 + k]) + 1e-6f;
            float inv2 = 1.f / (sig * sig);
            float cc = centres[g * 8 + k];
            A[k] = -0.5f * L2E * inv2;
            Bc[k] = L2E * cc * inv2;
            Gc[k] = -0.5f * L2E * cc * cc * inv2;
            W[k] = rbw[g * 8 + k];
        }
        float lw = linw[g];

        float s[8], cv[36];
#pragma unroll
        for (int f = 0; f < 8; f++) s[f] = 0.f;
#pragma unroll
        for (int i = 0; i < 36; i++) cv[i] = 0.f;

        for (int row = row0; row < B; row += rowsInFlight) {
            const float4* xv = reinterpret_cast<const float4*>(x + (size_t)row * 64 + g * 8);
            float4 xa = xv[0], xb = xv[1];
            float xf[8] = {xa.x, xa.y, xa.z, xa.w, xb.x, xb.y, xb.z, xb.w};
            float act[8];
#pragma unroll
            for (int f = 0; f < 8; f++) {
                float xvv = xf[f];
                float x2 = xvv * xvv;
                float acc = 0.f;
#pragma unroll
                for (int k = 0; k < 8; k++) {
                    float arg = fmaf(A[k], x2, fmaf(Bc[k], xvv, Gc[k]));
                    acc = fmaf(W[k], ex2f(arg), acc);
                }
                act[f] = fmaf(lw, xvv, acc);
            }
            float4 v0 = make_float4(act[0], act[1], act[2], act[3]);
            float4 v1 = make_float4(act[4], act[5], act[6], act[7]);
            *reinterpret_cast<float4*>(&g_act[(size_t)(2 * g) * B4 + (size_t)row * 4]) = v0;
            *reinterpret_cast<float4*>(&g_act[(size_t)(2 * g + 1) * B4 + (size_t)row * 4]) = v1;
#pragma unroll
            for (int f = 0; f < 8; f++) s[f] += act[f];
            int idx = 0;
#pragma unroll
            for (int f = 0; f < 8; f++)
#pragma unroll
                for (int f2 = 0; f2 <= f; f2++) {
                    cv[idx] = fmaf(act[f], act[f2], cv[idx]);
                    idx++;
                }
        }

#pragma unroll
        for (int f = 0; f < 8; f++) {
            s[f] += __shfl_xor_sync(0xffffffffu, s[f], 8);
            s[f] += __shfl_xor_sync(0xffffffffu, s[f], 16);
        }
#pragma unroll
        for (int i = 0; i < 36; i++) {
            cv[i] += __shfl_xor_sync(0xffffffffu, cv[i], 8);
            cv[i] += __shfl_xor_sync(0xffffffffu, cv[i], 16);
        }
        for (int i = tid; i < 352; i += NTHR) sm[i] = 0.f;
        __syncthreads();
        if ((tid & 31) < 8) {
#pragma unroll
            for (int f = 0; f < 8; f++) atomicAdd(&sm[g * 44 + f], s[f]);
#pragma unroll
            for (int i = 0; i < 36; i++) atomicAdd(&sm[g * 44 + 8 + i], cv[i]);
        }
        __syncthreads();
        for (int i = tid; i < 352; i += NTHR)
            atomicAdd(&g_statA[i], sm[i]);
    }

    grid_barrier(&g_bar1);

    // ================= P2: fold BN1, build M, fuzzy precompute (per block) ===
    {
        for (int i = tid; i < 352; i += NTHR) sm[i] = __ldcg(&g_statA[i]);
        __syncthreads();

        if (tid < 128) {
            int g = tid >> 4, o = tid & 15;
            float P[8];
#pragma unroll
            for (int f = 0; f < 8; f++) P[f] = pW[g * 128 + o * 8 + f];
            const float* gs = &sm[g * 44];
            float sum_h = 0.f;
#pragma unroll
            for (int f = 0; f < 8; f++) sum_h = fmaf(P[f], gs[f], sum_h);
            float ss = 0.f;
            int idx = 0;
#pragma unroll
            for (int f = 0; f < 8; f++)
#pragma unroll
                for (int f2 = 0; f2 <= f; f2++) {
                    float c = gs[8 + idx];
                    float w = (f == f2) ? P[f] * P[f] : 2.f * P[f] * P[f2];
                    ss = fmaf(w, c, ss);
                    idx++;
                }
            float mu = sum_h * invB;
            float var = fmaf(-mu, mu, ss * invB);
            s1sh[tid] = g1[tid] * rsqrtf(var + 1e-5f);
        }
        __syncthreads();

        for (int i = tid; i < 1280; i += NTHR) {
            int ch = i / 20, j = i % 20;
            int g = ch >> 3, f = ch & 7;
            float acc = 0.f;
#pragma unroll
            for (int o = 0; o < 16; o++) {
                int c = g * 16 + o;
                acc = fmaf(fpW[j * 128 + c] * s1sh[c], pW[g * 128 + o * 8 + f], acc);
            }
            Msh[ch * 20 + j] = acc;
        }
        for (int i = tid; i < 200; i += NTHR) {
            float su = __expf(lsu[i]) + 1e-6f;
            float sl = fminf(__expf(lsl[i]) + 1e-6f, 0.9f * su);
            float4 v;
            v.x = fzc[i];
            v.y = -0.5f * L2E / (su * su);
            v.z = -0.5f * L2E / (sl * sl);
            v.w = 0.f;
            fzsh[i] = v;
        }
        if (tid < 10) wrs[tid] = hW[tid] * (0.5f / 20.f);
        if (tid == 0) b0s = hb[0];
        __syncthreads();
    }

    // ================= P3: z~ = M * act (rows in smem), sumsq stats ==========
    {
        const ulonglong2* wp = reinterpret_cast<const ulonglong2*>(Msh);
        float qq[20];
#pragma unroll
        for (int j = 0; j < 20; j++) qq[j] = 0.f;

        int nchunk = B / (NBLK * NTHR);   // 2 for B=131072
        for (int c = 0; c < nchunk; c++) {
            int row = c * NBLK * NTHR + blockIdx.x * NTHR + tid;
            unsigned long long a0[10];
#pragma unroll
            for (int p = 0; p < 10; p++) a0[p] = 0ull;
#pragma unroll
            for (int q = 0; q < 16; q++) {
                float4 av = *reinterpret_cast<const float4*>(
                    &g_act[(size_t)q * B4 + (size_t)row * 4]);
                float af[4] = {av.x, av.y, av.z, av.w};
#pragma unroll
                for (int i = 0; i < 4; i++) {
                    int ch = q * 4 + i;
                    unsigned long long d0;
                    PACK_DUP(d0, af[i]);
#pragma unroll
                    for (int qd = 0; qd < 5; qd++) {
                        ulonglong2 w2 = wp[ch * 5 + qd];
                        FMA_F32X2(a0[2 * qd],     w2.x, d0, a0[2 * qd]);
                        FMA_F32X2(a0[2 * qd + 1], w2.y, d0, a0[2 * qd + 1]);
                    }
                }
            }
            float* zr = &zsh[(c * NTHR + tid) * ZP];
#pragma unroll
            for (int p = 0; p < 10; p++) {
                float zlo, zhi;
                UNPACK2(zlo, zhi, a0[p]);
                zr[2 * p] = zlo;
                zr[2 * p + 1] = zhi;
                qq[2 * p]     = fmaf(zlo, zlo, qq[2 * p]);
                qq[2 * p + 1] = fmaf(zhi, zhi, qq[2 * p + 1]);
            }
        }
#pragma unroll
        for (int j = 0; j < 20; j++) {
#pragma unroll
            for (int off = 16; off > 0; off >>= 1)
                qq[j] += __shfl_xor_sync(0xffffffffu, qq[j], off);
        }
        __syncthreads();                 // sm reuse safety
        if (tid < 20) sm[tid] = 0.f;
        __syncthreads();
        if ((tid & 31) == 0) {
#pragma unroll
            for (int j = 0; j < 20; j++) atomicAdd(&sm[j], qq[j]);
        }
        __syncthreads();
        if (tid < 20) atomicAdd(&g_stat2[tid], sm[tid]);
    }

    grid_barrier(&g_bar2);

    // ================= P4: BN2 affine + GELU + fuzzy + head ==================
    {
        if (tid < 20) {
            int j = tid;
            float mu = 0.f;
#pragma unroll 8
            for (int ch = 0; ch < 64; ch++) {
                int g = ch >> 3, f = ch & 7;
                mu = fmaf(Msh[ch * 20 + j], __ldcg(&g_statA[g * 44 + f]), mu);
            }
            mu *= invB;
            float var = fmaf(-mu, mu, __ldcg(&g_stat2[j]) * invB);
            float sc = g2v[j] * rsqrtf(var + 1e-5f);
            s2s[j] = sc;
            t2s[j] = b2v[j] - mu * sc;
        }
        __syncthreads();

        int nchunk = B / (NBLK * NTHR);
        for (int c = 0; c < nchunk; c++) {
            int row = c * NBLK * NTHR + blockIdx.x * NTHR + tid;
            const float* zr = &zsh[(c * NTHR + tid) * ZP];
            float z[20];
#pragma unroll
            for (int j = 0; j < 20; j++) {
                float v = fmaf(zr[j], s2s[j], t2s[j]);
                z[j] = 0.5f * v * (1.f + erff(v * 0.70710678118654752f));
            }
            float o = b0s;
#pragma unroll
            for (int r = 0; r < 10; r++) {
                float S = 0.f;
#pragma unroll
                for (int d = 0; d < 20; d++) {
                    float4 p = fzsh[r * 20 + d];
                    float df = z[d] - p.x;
                    float d2 = df * df;
                    S += ex2f(p.y * d2) + ex2f(p.z * d2);
                }
                o = fmaf(wrs[r], S, o);
            }
            out[row] = o;
        }
    }
}

// ---------------- launcher ----------------
extern "C" void kernel_launch(void* const* d_in, const int* in_sizes, int n_in,
                              void* d_out, int out_size) {
    const float* x        = (const float*)d_in[0];
    const float* centres  = (const float*)d_in[1];
    const float* logw     = (const float*)d_in[2];
    const float* rbw      = (const float*)d_in[3];
    const float* linw     = (const float*)d_in[4];
    const float* pW       = (const float*)d_in[5];
    /* d_in[6] = proj_b   — folds into z~ constant, cancels through BN2 */
    const float* bn1g     = (const float*)d_in[7];
    /* d_in[8] = bn1_beta  — cancels through BN2 */
    const float* fpW      = (const float*)d_in[9];
    /* d_in[10] = fp_b     — cancels through BN2 */
    const float* bn2g     = (const float*)d_in[11];
    const float* bn2b     = (const float*)d_in[12];
    const float* fzc      = (const float*)d_in[13];
    const float* lsu      = (const float*)d_in[14];
    const float* lsl      = (const float*)d_in[15];
    const float* hW       = (const float*)d_in[16];
    const float* hb       = (const float*)d_in[17];
    float* out = (float*)d_out;

    int B = in_sizes[0] / 64;
    float invB = 1.0f / (float)B;

    k0_zero<<<1, 512>>>();
    k_fused<<<NBLK, NTHR>>>(x, centres, logw, rbw, linw, pW, bn1g, fpW,
                            bn2g, bn2b, fzc, lsu, lsl, hW, hb, out, B, invB);
}

// round 11
// speedup vs baseline: 3.2401x; 3.2401x over previous
#include <cuda_runtime.h>
#include <cstdint>

#define L2E 1.4426950408889634f
#define BMAX 131072

// ---------------- device scratch (static, no runtime alloc) ----------------
// act in quad-interleaved layout: [16 quads][B][4], quad q holds channels 4q..4q+3
__device__ float g_act[64u * BMAX];
__device__ float g_z[20u * BMAX];       // z~^T, channel-major [20][B]
__device__ float g_statA[352];          // per group: 8 sums + 36 sym-cov (44 each)
__device__ float g_stat2[20];           // sumsq[20] of z~
__device__ float g_M[64 * 20];          // combined weights, layout [ch][j]
__device__ float4 g_fz[200];            // (centre, au, al, 0) per (rule, dim)
__device__ float g_wr[10];              // head weight * 0.5/FIN
__device__ float g_b0;                  // head bias

__device__ __forceinline__ float ex2f(float x) {
    float y; asm("ex2.approx.ftz.f32 %0, %1;" : "=f"(y) : "f"(x)); return y;
}

#define FMA_F32X2(d, a, b, c) \
    asm("fma.rn.f32x2 %0, %1, %2, %3;" : "=l"(d) : "l"(a), "l"(b), "l"(c))
#define PACK_DUP(d, f) \
    asm("mov.b64 %0, {%1, %1};" : "=l"(d) : "f"(f))
#define UNPACK2(lo, hi, v) \
    asm("mov.b64 {%0, %1}, %2;" : "=f"(lo), "=f"(hi) : "l"(v))

// ---------------- K0: zero accumulators ----------------
__global__ void k0_zero() {
    int t = threadIdx.x;
    if (t < 352) g_statA[t] = 0.f;
    if (t < 20)  g_stat2[t] = 0.f;
}

// ---------------- K1: act = KAN-RBF(x), accumulate per-group act stats -----
__global__ __launch_bounds__(256, 2) void k1_kan(
    const float* __restrict__ x,
    const float* __restrict__ centres,   // [8][8]
    const float* __restrict__ logw,      // [8][8]
    const float* __restrict__ rbw,       // [8][8]
    const float* __restrict__ linw,      // [8]
    int B, int rowsInFlight)
{
    int slot = blockIdx.x * 256 + threadIdx.x;
    int g = slot & 7;
    int row0 = slot >> 3;
    size_t B4 = (size_t)B * 4;

    float A[8], Bc[8], Gc[8], W[8];
#pragma unroll
    for (int k = 0; k < 8; k++) {
        float sig = __expf(logw[g * 8 + k]) + 1e-6f;
        float inv2 = 1.f / (sig * sig);
        float cc = centres[g * 8 + k];
        A[k] = -0.5f * L2E * inv2;
        Bc[k] = L2E * cc * inv2;
        Gc[k] = -0.5f * L2E * cc * cc * inv2;
        W[k] = rbw[g * 8 + k];
    }
    float lw = linw[g];

    float s[8], cv[36];
#pragma unroll
    for (int f = 0; f < 8; f++) s[f] = 0.f;
#pragma unroll
    for (int i = 0; i < 36; i++) cv[i] = 0.f;

    for (int row = row0; row < B; row += rowsInFlight) {
        const float4* xv = reinterpret_cast<const float4*>(x + (size_t)row * 64 + g * 8);
        float4 xa = xv[0], xb = xv[1];
        float xf[8] = {xa.x, xa.y, xa.z, xa.w, xb.x, xb.y, xb.z, xb.w};
        float act[8];
#pragma unroll
        for (int f = 0; f < 8; f++) {
            float xvv = xf[f];
            float x2 = xvv * xvv;
            float acc = 0.f;
#pragma unroll
            for (int k = 0; k < 8; k++) {
                float arg = fmaf(A[k], x2, fmaf(Bc[k], xvv, Gc[k]));
                acc = fmaf(W[k], ex2f(arg), acc);
            }
            act[f] = fmaf(lw, xvv, acc);
        }
        float4 v0 = make_float4(act[0], act[1], act[2], act[3]);
        float4 v1 = make_float4(act[4], act[5], act[6], act[7]);
        *reinterpret_cast<float4*>(&g_act[(size_t)(2 * g) * B4 + (size_t)row * 4]) = v0;
        *reinterpret_cast<float4*>(&g_act[(size_t)(2 * g + 1) * B4 + (size_t)row * 4]) = v1;
#pragma unroll
        for (int f = 0; f < 8; f++) s[f] += act[f];
        int idx = 0;
#pragma unroll
        for (int f = 0; f < 8; f++)
#pragma unroll
            for (int f2 = 0; f2 <= f; f2++) {
                cv[idx] = fmaf(act[f], act[f2], cv[idx]);
                idx++;
            }
    }

#pragma unroll
    for (int f = 0; f < 8; f++) {
        s[f] += __shfl_xor_sync(0xffffffffu, s[f], 8);
        s[f] += __shfl_xor_sync(0xffffffffu, s[f], 16);
    }
#pragma unroll
    for (int i = 0; i < 36; i++) {
        cv[i] += __shfl_xor_sync(0xffffffffu, cv[i], 8);
        cv[i] += __shfl_xor_sync(0xffffffffu, cv[i], 16);
    }
    __shared__ float sm[352];
    for (int i = threadIdx.x; i < 352; i += 256) sm[i] = 0.f;
    __syncthreads();
    if ((threadIdx.x & 31) < 8) {
#pragma unroll
        for (int f = 0; f < 8; f++) atomicAdd(&sm[g * 44 + f], s[f]);
#pragma unroll
        for (int i = 0; i < 36; i++) atomicAdd(&sm[g * 44 + 8 + i], cv[i]);
    }
    __syncthreads();
    for (int i = threadIdx.x; i < 352; i += 256)
        atomicAdd(&g_statA[i], sm[i]);
}

// ---------------- K2: BN1 var from cov; build M = Wf_folded * blockdiag(P) --
__global__ void k2_fold(
    const float* __restrict__ g1,        // bn1_gamma [128]
    const float* __restrict__ pW,        // [8][16][8]
    const float* __restrict__ fpW,       // [20][128]
    const float* __restrict__ fzc,       // [10][20]
    const float* __restrict__ lsu,       // [10][20]
    const float* __restrict__ lsl,       // [10][20]
    const float* __restrict__ hW,        // [1][10]
    const float* __restrict__ hb,        // [1]
    float invB)
{
    __shared__ float st[352];
    __shared__ float s1sh[128];
    int t = threadIdx.x;
    for (int i = t; i < 352; i += blockDim.x) st[i] = g_statA[i];
    __syncthreads();

    if (t < 128) {
        int g = t >> 4, o = t & 15;
        float P[8];
#pragma unroll
        for (int f = 0; f < 8; f++) P[f] = pW[g * 128 + o * 8 + f];
        const float* gs = &st[g * 44];
        float sum_h = 0.f;
#pragma unroll
        for (int f = 0; f < 8; f++) sum_h = fmaf(P[f], gs[f], sum_h);
        float ss = 0.f;
        int idx = 0;
#pragma unroll
        for (int f = 0; f < 8; f++)
#pragma unroll
            for (int f2 = 0; f2 <= f; f2++) {
                float c = gs[8 + idx];
                float w = (f == f2) ? P[f] * P[f] : 2.f * P[f] * P[f2];
                ss = fmaf(w, c, ss);
                idx++;
            }
        float mu = sum_h * invB;
        float var = fmaf(-mu, mu, ss * invB);
        s1sh[t] = g1[t] * rsqrtf(var + 1e-5f);
    }
    __syncthreads();

    for (int i = t; i < 1280; i += blockDim.x) {
        int ch = i / 20, j = i % 20;
        int g = ch >> 3, f = ch & 7;
        float acc = 0.f;
#pragma unroll
        for (int o = 0; o < 16; o++) {
            int c = g * 16 + o;
            acc = fmaf(fpW[j * 128 + c] * s1sh[c], pW[g * 128 + o * 8 + f], acc);
        }
        g_M[ch * 20 + j] = acc;
    }

    for (int i = t; i < 200; i += blockDim.x) {
        float su = __expf(lsu[i]) + 1e-6f;
        float sl = fminf(__expf(lsl[i]) + 1e-6f, 0.9f * su);
        float4 v;
        v.x = fzc[i];
        v.y = -0.5f * L2E / (su * su);
        v.z = -0.5f * L2E / (sl * sl);
        v.w = 0.f;
        g_fz[i] = v;
    }
    if (t < 10) g_wr[t] = hW[t] * (0.5f / 20.f);
    if (t == 0) g_b0 = hb[0];
}

// ---------------- K3: z~ = act @ M^T, channel-split across thread pairs ----
// 512 threads/block: half 0 = quads 0-7 (ch 0-31), half 1 = quads 8-15.
// Partials exchanged via padded smem; half h finalizes dims h*10..h*10+9.
__global__ __launch_bounds__(512) void k3_gemm(int B) {
    __shared__ float ws[1280];           // M [ch][j]
    __shared__ float sq[20];
    __shared__ float partA[256][11];     // half1 -> dims 0-9 partials
    __shared__ float partB[256][11];     // half0 -> dims 10-19 partials
    int tid = threadIdx.x;
    int half = tid >> 8;
    int lane = tid & 255;
    for (int i = tid; i < 1280; i += 512) ws[i] = g_M[i];
    if (tid < 20) sq[tid] = 0.f;
    __syncthreads();
    const ulonglong2* wp = reinterpret_cast<const ulonglong2*>(ws);

    int row = blockIdx.x * 256 + lane;
    size_t B4 = (size_t)B * 4;
    int qbase = half * 8;

    unsigned long long a0[10];
#pragma unroll
    for (int p = 0; p < 10; p++) a0[p] = 0ull;

#pragma unroll
    for (int q = 0; q < 8; q++) {
        float4 av = *reinterpret_cast<const float4*>(
            &g_act[(size_t)(qbase + q) * B4 + (size_t)row * 4]);
        float af[4] = {av.x, av.y, av.z, av.w};
#pragma unroll
        for (int i = 0; i < 4; i++) {
            int ch = (qbase + q) * 4 + i;
            unsigned long long d0;
            PACK_DUP(d0, af[i]);
#pragma unroll
            for (int qd = 0; qd < 5; qd++) {
                ulonglong2 w2 = wp[ch * 5 + qd];
                FMA_F32X2(a0[2 * qd],     w2.x, d0, a0[2 * qd]);
                FMA_F32X2(a0[2 * qd + 1], w2.y, d0, a0[2 * qd + 1]);
            }
        }
    }

    // exchange the other half's dims
    if (half == 0) {
#pragma unroll
        for (int p = 5; p < 10; p++) {
            float lo, hi; UNPACK2(lo, hi, a0[p]);
            partB[lane][2 * (p - 5)]     = lo;
            partB[lane][2 * (p - 5) + 1] = hi;
        }
    } else {
#pragma unroll
        for (int p = 0; p < 5; p++) {
            float lo, hi; UNPACK2(lo, hi, a0[p]);
            partA[lane][2 * p]     = lo;
            partA[lane][2 * p + 1] = hi;
        }
    }
    __syncthreads();

    float qq[10];
    if (half == 0) {
#pragma unroll
        for (int p = 0; p < 5; p++) {
            float lo, hi; UNPACK2(lo, hi, a0[p]);
            lo += partA[lane][2 * p];
            hi += partA[lane][2 * p + 1];
            g_z[(size_t)(2 * p) * B + row]     = lo;
            g_z[(size_t)(2 * p + 1) * B + row] = hi;
            qq[2 * p] = lo * lo;
            qq[2 * p + 1] = hi * hi;
        }
    } else {
#pragma unroll
        for (int p = 5; p < 10; p++) {
            float lo, hi; UNPACK2(lo, hi, a0[p]);
            lo += partB[lane][2 * (p - 5)];
            hi += partB[lane][2 * (p - 5) + 1];
            g_z[(size_t)(2 * p) * B + row]     = lo;
            g_z[(size_t)(2 * p + 1) * B + row] = hi;
            qq[2 * (p - 5)] = lo * lo;
            qq[2 * (p - 5) + 1] = hi * hi;
        }
    }
#pragma unroll
    for (int j = 0; j < 10; j++) {
#pragma unroll
        for (int off = 16; off > 0; off >>= 1)
            qq[j] += __shfl_xor_sync(0xffffffffu, qq[j], off);
    }
    if ((tid & 31) == 0) {
#pragma unroll
        for (int j = 0; j < 10; j++) atomicAdd(&sq[half * 10 + j], qq[j]);
    }
    __syncthreads();
    if (tid < 20) atomicAdd(&g_stat2[tid], sq[tid]);
}

// ---------------- K5: BN2 affine (fused K4) + GELU + IT2 fuzzy + head ------
__global__ __launch_bounds__(256) void k5_fuzzy(
    float* __restrict__ out,
    const float* __restrict__ g2, const float* __restrict__ b2,
    int B, float invB)
{
    __shared__ float4 fz[200];
    __shared__ float s2s[20], t2s[20], wrs[10];
    __shared__ float b0s;
    // fused BN2 finalize (redundant per block, trivial)
    if (threadIdx.x < 20) {
        int j = threadIdx.x;
        float mu = 0.f;
#pragma unroll 8
        for (int ch = 0; ch < 64; ch++) {
            int g = ch >> 3, f = ch & 7;
            mu = fmaf(g_M[ch * 20 + j], g_statA[g * 44 + f], mu);
        }
        mu *= invB;
        float var = fmaf(-mu, mu, g_stat2[j] * invB);
        float sc = g2[j] * rsqrtf(var + 1e-5f);
        s2s[j] = sc;
        t2s[j] = b2[j] - mu * sc;
    }
    for (int i = threadIdx.x; i < 200; i += 256) fz[i] = g_fz[i];
    if (threadIdx.x < 10) wrs[threadIdx.x] = g_wr[threadIdx.x];
    if (threadIdx.x == 0) b0s = g_b0;
    __syncthreads();

    int row = blockIdx.x * 256 + threadIdx.x;
    if (row < B) {
        float z[20];
#pragma unroll
        for (int j = 0; j < 20; j++) {
            float v = fmaf(g_z[(size_t)j * B + row], s2s[j], t2s[j]);
            z[j] = 0.5f * v * (1.f + erff(v * 0.70710678118654752f));
        }
        float o = b0s;
#pragma unroll
        for (int r = 0; r < 10; r++) {
            float S = 0.f;
#pragma unroll
            for (int d = 0; d < 20; d++) {
                float4 p = fz[r * 20 + d];
                float df = z[d] - p.x;
                float d2 = df * df;
                S += ex2f(p.y * d2) + ex2f(p.z * d2);
            }
            o = fmaf(wrs[r], S, o);
        }
        out[row] = o;
    }
}

// ---------------- launcher ----------------
extern "C" void kernel_launch(void* const* d_in, const int* in_sizes, int n_in,
                              void* d_out, int out_size) {
    const float* x        = (const float*)d_in[0];
    const float* centres  = (const float*)d_in[1];
    const float* logw     = (const float*)d_in[2];
    const float* rbw      = (const float*)d_in[3];
    const float* linw     = (const float*)d_in[4];
    const float* pW       = (const float*)d_in[5];
    /* d_in[6] = proj_b   — folds into z~ constant, cancels through BN2 */
    const float* bn1g     = (const float*)d_in[7];
    /* d_in[8] = bn1_beta  — cancels through BN2 */
    const float* fpW      = (const float*)d_in[9];
    /* d_in[10] = fp_b     — cancels through BN2 */
    const float* bn2g     = (const float*)d_in[11];
    const float* bn2b     = (const float*)d_in[12];
    const float* fzc      = (const float*)d_in[13];
    const float* lsu      = (const float*)d_in[14];
    const float* lsl      = (const float*)d_in[15];
    const float* hW       = (const float*)d_in[16];
    const float* hb       = (const float*)d_in[17];
    float* out = (float*)d_out;

    int B = in_sizes[0] / 64;
    float invB = 1.0f / (float)B;

    k0_zero<<<1, 512>>>();

    const int NB1 = 296;
    k1_kan<<<NB1, 256>>>(x, centres, logw, rbw, linw, B, NB1 * 32);

    k2_fold<<<1, 256>>>(bn1g, pW, fpW, fzc, lsu, lsl, hW, hb, invB);

    k3_gemm<<<B / 256, 512>>>(B);

    k5_fuzzy<<<B / 256, 256>>>(out, bn2g, bn2b, B, invB);
}

// round 12
// speedup vs baseline: 3.7614x; 1.1609x over previous
#include <cuda_runtime.h>
#include <cstdint>

#define L2E 1.4426950408889634f
#define BMAX 131072

// ---------------- device scratch (static, no runtime alloc) ----------------
// act in quad-interleaved layout: [16 quads][B][4], quad q holds channels 4q..4q+3
__device__ float g_act[64u * BMAX];
__device__ float g_z[20u * BMAX];       // z~^T, channel-major [20][B]
__device__ float g_statA[352];          // per group: 8 sums + 36 sym-cov (44 each)
__device__ float g_stat2[20];           // sumsq[20] of z~
__device__ float g_M[64 * 20];          // combined weights, layout [ch][j]
__device__ float4 g_fz[200];            // (centre, au, al, 0) per (rule, dim)
__device__ float g_wr[10];              // head weight * 0.5/FIN
__device__ float g_b0;                  // head bias

__device__ __forceinline__ float ex2f(float x) {
    float y; asm("ex2.approx.ftz.f32 %0, %1;" : "=f"(y) : "f"(x)); return y;
}

#define FMA_F32X2(d, a, b, c) \
    asm("fma.rn.f32x2 %0, %1, %2, %3;" : "=l"(d) : "l"(a), "l"(b), "l"(c))
#define PACK_DUP(d, f) \
    asm("mov.b64 %0, {%1, %1};" : "=l"(d) : "f"(f))
#define PACK2(d, lo, hi) \
    asm("mov.b64 %0, {%1, %2};" : "=l"(d) : "f"(lo), "f"(hi))
#define UNPACK2(lo, hi, v) \
    asm("mov.b64 {%0, %1}, %2;" : "=f"(lo), "=f"(hi) : "l"(v))

// ---------------- K0: zero accumulators ----------------
__global__ void k0_zero() {
    int t = threadIdx.x;
    if (t < 352) g_statA[t] = 0.f;
    if (t < 20)  g_stat2[t] = 0.f;
}

// ---------------- K1: act = KAN-RBF(x), per-group stats; f32x2-packed RBF --
__global__ __launch_bounds__(256, 2) void k1_kan(
    const float* __restrict__ x,
    const float* __restrict__ centres,   // [8][8]
    const float* __restrict__ logw,      // [8][8]
    const float* __restrict__ rbw,       // [8][8]
    const float* __restrict__ linw,      // [8]
    int B, int rowsInFlight)
{
    int slot = blockIdx.x * 256 + threadIdx.x;
    int g = slot & 7;
    int row0 = slot >> 3;
    size_t B4 = (size_t)B * 4;

    // packed per-pair RBF coefficients (k pairs: {0,1},{2,3},{4,5},{6,7})
    unsigned long long Ap[4], Bp[4], Gp[4], Wp[4];
#pragma unroll
    for (int kp = 0; kp < 4; kp++) {
        float a2[2], b2[2], g2[2], w2[2];
#pragma unroll
        for (int h = 0; h < 2; h++) {
            int k = 2 * kp + h;
            float sig = __expf(logw[g * 8 + k]) + 1e-6f;
            float inv2 = 1.f / (sig * sig);
            float cc = centres[g * 8 + k];
            a2[h] = -0.5f * L2E * inv2;
            b2[h] = L2E * cc * inv2;
            g2[h] = -0.5f * L2E * cc * cc * inv2;
            w2[h] = rbw[g * 8 + k];
        }
        PACK2(Ap[kp], a2[0], a2[1]);
        PACK2(Bp[kp], b2[0], b2[1]);
        PACK2(Gp[kp], g2[0], g2[1]);
        PACK2(Wp[kp], w2[0], w2[1]);
    }
    float lw = linw[g];

    float s[8], cv[36];
#pragma unroll
    for (int f = 0; f < 8; f++) s[f] = 0.f;
#pragma unroll
    for (int i = 0; i < 36; i++) cv[i] = 0.f;

    for (int row = row0; row < B; row += rowsInFlight) {
        const float4* xv = reinterpret_cast<const float4*>(x + (size_t)row * 64 + g * 8);
        float4 xa = xv[0], xb = xv[1];
        float xf[8] = {xa.x, xa.y, xa.z, xa.w, xb.x, xb.y, xb.z, xb.w};
        float act[8];
#pragma unroll
        for (int f = 0; f < 8; f++) {
            float xvv = xf[f];
            float x2 = xvv * xvv;
            unsigned long long xd, x2d;
            PACK_DUP(xd, xvv);
            PACK_DUP(x2d, x2);
            float e[8];
#pragma unroll
            for (int kp = 0; kp < 4; kp++) {
                unsigned long long arg;
                FMA_F32X2(arg, Bp[kp], xd, Gp[kp]);
                FMA_F32X2(arg, Ap[kp], x2d, arg);
                float lo, hi; UNPACK2(lo, hi, arg);
                e[2 * kp] = ex2f(lo);
                e[2 * kp + 1] = ex2f(hi);
            }
            unsigned long long accp = 0ull;
#pragma unroll
            for (int kp = 0; kp < 4; kp++) {
                unsigned long long ep;
                PACK2(ep, e[2 * kp], e[2 * kp + 1]);
                FMA_F32X2(accp, Wp[kp], ep, accp);
            }
            float alo, ahi; UNPACK2(alo, ahi, accp);
            act[f] = fmaf(lw, xvv, alo + ahi);
        }
        float4 v0 = make_float4(act[0], act[1], act[2], act[3]);
        float4 v1 = make_float4(act[4], act[5], act[6], act[7]);
        *reinterpret_cast<float4*>(&g_act[(size_t)(2 * g) * B4 + (size_t)row * 4]) = v0;
        *reinterpret_cast<float4*>(&g_act[(size_t)(2 * g + 1) * B4 + (size_t)row * 4]) = v1;
#pragma unroll
        for (int f = 0; f < 8; f++) s[f] += act[f];
        int idx = 0;
#pragma unroll
        for (int f = 0; f < 8; f++)
#pragma unroll
            for (int f2 = 0; f2 <= f; f2++) {
                cv[idx] = fmaf(act[f], act[f2], cv[idx]);
                idx++;
            }
    }

#pragma unroll
    for (int f = 0; f < 8; f++) {
        s[f] += __shfl_xor_sync(0xffffffffu, s[f], 8);
        s[f] += __shfl_xor_sync(0xffffffffu, s[f], 16);
    }
#pragma unroll
    for (int i = 0; i < 36; i++) {
        cv[i] += __shfl_xor_sync(0xffffffffu, cv[i], 8);
        cv[i] += __shfl_xor_sync(0xffffffffu, cv[i], 16);
    }
    __shared__ float sm[352];
    for (int i = threadIdx.x; i < 352; i += 256) sm[i] = 0.f;
    __syncthreads();
    if ((threadIdx.x & 31) < 8) {
#pragma unroll
        for (int f = 0; f < 8; f++) atomicAdd(&sm[g * 44 + f], s[f]);
#pragma unroll
        for (int i = 0; i < 36; i++) atomicAdd(&sm[g * 44 + 8 + i], cv[i]);
    }
    __syncthreads();
    for (int i = threadIdx.x; i < 352; i += 256)
        atomicAdd(&g_statA[i], sm[i]);
}

// ---------------- K2: BN1 var from cov; build M = Wf_folded * blockdiag(P) --
__global__ void k2_fold(
    const float* __restrict__ g1,        // bn1_gamma [128]
    const float* __restrict__ pW,        // [8][16][8]
    const float* __restrict__ fpW,       // [20][128]
    const float* __restrict__ fzc,       // [10][20]
    const float* __restrict__ lsu,       // [10][20]
    const float* __restrict__ lsl,       // [10][20]
    const float* __restrict__ hW,        // [1][10]
    const float* __restrict__ hb,        // [1]
    float invB)
{
    __shared__ float st[352];
    __shared__ float s1sh[128];
    int t = threadIdx.x;
    for (int i = t; i < 352; i += blockDim.x) st[i] = g_statA[i];
    __syncthreads();

    if (t < 128) {
        int g = t >> 4, o = t & 15;
        float P[8];
#pragma unroll
        for (int f = 0; f < 8; f++) P[f] = pW[g * 128 + o * 8 + f];
        const float* gs = &st[g * 44];
        float sum_h = 0.f;
#pragma unroll
        for (int f = 0; f < 8; f++) sum_h = fmaf(P[f], gs[f], sum_h);
        float ss = 0.f;
        int idx = 0;
#pragma unroll
        for (int f = 0; f < 8; f++)
#pragma unroll
            for (int f2 = 0; f2 <= f; f2++) {
                float c = gs[8 + idx];
                float w = (f == f2) ? P[f] * P[f] : 2.f * P[f] * P[f2];
                ss = fmaf(w, c, ss);
                idx++;
            }
        float mu = sum_h * invB;
        float var = fmaf(-mu, mu, ss * invB);
        s1sh[t] = g1[t] * rsqrtf(var + 1e-5f);
    }
    __syncthreads();

    for (int i = t; i < 1280; i += blockDim.x) {
        int ch = i / 20, j = i % 20;
        int g = ch >> 3, f = ch & 7;
        float acc = 0.f;
#pragma unroll
        for (int o = 0; o < 16; o++) {
            int c = g * 16 + o;
            acc = fmaf(fpW[j * 128 + c] * s1sh[c], pW[g * 128 + o * 8 + f], acc);
        }
        g_M[ch * 20 + j] = acc;
    }

    for (int i = t; i < 200; i += blockDim.x) {
        float su = __expf(lsu[i]) + 1e-6f;
        float sl = fminf(__expf(lsl[i]) + 1e-6f, 0.9f * su);
        float4 v;
        v.x = fzc[i];
        v.y = -0.5f * L2E / (su * su);
        v.z = -0.5f * L2E / (sl * sl);
        v.w = 0.f;
        g_fz[i] = v;
    }
    if (t < 10) g_wr[t] = hW[t] * (0.5f / 20.f);
    if (t == 0) g_b0 = hb[0];
}

// ---------------- K3: z~ = act @ M^T, TWO rows per thread ------------------
// Weight LDS amortized over 2 rows (smem crossbar was the binder).
__global__ __launch_bounds__(256) void k3_gemm(int B) {
    __shared__ float ws[1280];           // M [ch][j]
    __shared__ float sq[20];
    for (int i = threadIdx.x; i < 1280; i += 256) ws[i] = g_M[i];
    if (threadIdx.x < 20) sq[threadIdx.x] = 0.f;
    __syncthreads();
    const ulonglong2* wp = reinterpret_cast<const ulonglong2*>(ws);

    int row = (blockIdx.x * 256 + threadIdx.x) * 2;
    size_t B4 = (size_t)B * 4;

    unsigned long long a0[10], a1[10];
#pragma unroll
    for (int p = 0; p < 10; p++) { a0[p] = 0ull; a1[p] = 0ull; }

#pragma unroll
    for (int q = 0; q < 16; q++) {
        const float4* base = reinterpret_cast<const float4*>(
            &g_act[(size_t)q * B4 + (size_t)row * 4]);
        float4 av0 = base[0];
        float4 av1 = base[1];
        float af0[4] = {av0.x, av0.y, av0.z, av0.w};
        float af1[4] = {av1.x, av1.y, av1.z, av1.w};
#pragma unroll
        for (int i = 0; i < 4; i++) {
            int ch = q * 4 + i;
            unsigned long long d0, d1;
            PACK_DUP(d0, af0[i]);
            PACK_DUP(d1, af1[i]);
#pragma unroll
            for (int qd = 0; qd < 5; qd++) {
                ulonglong2 w2 = wp[ch * 5 + qd];
                FMA_F32X2(a0[2 * qd],     w2.x, d0, a0[2 * qd]);
                FMA_F32X2(a0[2 * qd + 1], w2.y, d0, a0[2 * qd + 1]);
                FMA_F32X2(a1[2 * qd],     w2.x, d1, a1[2 * qd]);
                FMA_F32X2(a1[2 * qd + 1], w2.y, d1, a1[2 * qd + 1]);
            }
        }
    }

    float qq[20];
#pragma unroll
    for (int p = 0; p < 10; p++) {
        float z0lo, z0hi, z1lo, z1hi;
        UNPACK2(z0lo, z0hi, a0[p]);
        UNPACK2(z1lo, z1hi, a1[p]);
        int j0 = 2 * p, j1 = 2 * p + 1;
        *reinterpret_cast<float2*>(&g_z[(size_t)j0 * B + row]) = make_float2(z0lo, z1lo);
        *reinterpret_cast<float2*>(&g_z[(size_t)j1 * B + row]) = make_float2(z0hi, z1hi);
        qq[j0] = fmaf(z0lo, z0lo, z1lo * z1lo);
        qq[j1] = fmaf(z0hi, z0hi, z1hi * z1hi);
    }
#pragma unroll
    for (int j = 0; j < 20; j++) {
#pragma unroll
        for (int off = 16; off > 0; off >>= 1)
            qq[j] += __shfl_xor_sync(0xffffffffu, qq[j], off);
    }
    if ((threadIdx.x & 31) == 0) {
#pragma unroll
        for (int j = 0; j < 20; j++) atomicAdd(&sq[j], qq[j]);
    }
    __syncthreads();
    if (threadIdx.x < 20) atomicAdd(&g_stat2[threadIdx.x], sq[threadIdx.x]);
}

// ---------------- K5: BN2 affine (fused K4) + GELU + IT2 fuzzy + head ------
__global__ __launch_bounds__(256) void k5_fuzzy(
    float* __restrict__ out,
    const float* __restrict__ g2, const float* __restrict__ b2,
    int B, float invB)
{
    __shared__ float4 fz[200];
    __shared__ float s2s[20], t2s[20], wrs[10];
    __shared__ float b0s;
    if (threadIdx.x < 20) {
        int j = threadIdx.x;
        float mu = 0.f;
#pragma unroll 8
        for (int ch = 0; ch < 64; ch++) {
            int g = ch >> 3, f = ch & 7;
            mu = fmaf(g_M[ch * 20 + j], g_statA[g * 44 + f], mu);
        }
        mu *= invB;
        float var = fmaf(-mu, mu, g_stat2[j] * invB);
        float sc = g2[j] * rsqrtf(var + 1e-5f);
        s2s[j] = sc;
        t2s[j] = b2[j] - mu * sc;
    }
    for (int i = threadIdx.x; i < 200; i += 256) fz[i] = g_fz[i];
    if (threadIdx.x < 10) wrs[threadIdx.x] = g_wr[threadIdx.x];
    if (threadIdx.x == 0) b0s = g_b0;
    __syncthreads();

    int row = blockIdx.x * 256 + threadIdx.x;
    if (row < B) {
        float z[20];
#pragma unroll
        for (int j = 0; j < 20; j++) {
            float v = fmaf(g_z[(size_t)j * B + row], s2s[j], t2s[j]);
            z[j] = 0.5f * v * (1.f + erff(v * 0.70710678118654752f));
        }
        float o = b0s;
#pragma unroll
        for (int r = 0; r < 10; r++) {
            float S = 0.f;
#pragma unroll
            for (int d = 0; d < 20; d++) {
                float4 p = fz[r * 20 + d];
                float df = z[d] - p.x;
                float d2 = df * df;
                S += ex2f(p.y * d2) + ex2f(p.z * d2);
            }
            o = fmaf(wrs[r], S, o);
        }
        out[row] = o;
    }
}

// ---------------- launcher ----------------
extern "C" void kernel_launch(void* const* d_in, const int* in_sizes, int n_in,
                              void* d_out, int out_size) {
    const float* x        = (const float*)d_in[0];
    const float* centres  = (const float*)d_in[1];
    const float* logw     = (const float*)d_in[2];
    const float* rbw      = (const float*)d_in[3];
    const float* linw     = (const float*)d_in[4];
    const float* pW       = (const float*)d_in[5];
    /* d_in[6] = proj_b   — folds into z~ constant, cancels through BN2 */
    const float* bn1g     = (const float*)d_in[7];
    /* d_in[8] = bn1_beta  — cancels through BN2 */
    const float* fpW      = (const float*)d_in[9];
    /* d_in[10] = fp_b     — cancels through BN2 */
    const float* bn2g     = (const float*)d_in[11];
    const float* bn2b     = (const float*)d_in[12];
    const float* fzc      = (const float*)d_in[13];
    const float* lsu      = (const float*)d_in[14];
    const float* lsl      = (const float*)d_in[15];
    const float* hW       = (const float*)d_in[16];
    const float* hb       = (const float*)d_in[17];
    float* out = (float*)d_out;

    int B = in_sizes[0] / 64;
    float invB = 1.0f / (float)B;

    k0_zero<<<1, 512>>>();

    const int NB1 = 296;
    k1_kan<<<NB1, 256>>>(x, centres, logw, rbw, linw, B, NB1 * 32);

    k2_fold<<<1, 256>>>(bn1g, pW, fpW, fzc, lsu, lsl, hW, hb, invB);

    k3_gemm<<<B / 512, 256>>>(B);

    k5_fuzzy<<<B / 256, 256>>>(out, bn2g, bn2b, B, invB);
}